// round 11
// baseline (speedup 1.0000x reference)
#include <cuda_runtime.h>
#include <cstdint>

#define S_LEN  4096
#define BATCH  2
#define DMODEL 768
#define NHEAD  12
#define HDIM   64
#define WSZ    256
#define NROWS  (S_LEN * BATCH)   // 8192

// scratch (device globals: allowed, no allocation)
__device__ float g_q [(size_t)NROWS * DMODEL];
__device__ float g_k [(size_t)NROWS * DMODEL];
__device__ float g_v [(size_t)NROWS * DMODEL];
__device__ float g_ar[(size_t)NROWS * DMODEL];        // tf32-rounded activations
__device__ float g_w3[(size_t)3 * DMODEL * DMODEL];   // tf32-rounded W (row-major)

// ---------------------------------------------------------------------------
// helpers
// ---------------------------------------------------------------------------
__device__ __forceinline__ float tf32f(float x) {
    uint32_t u;
    asm("cvt.rna.tf32.f32 %0,%1;" : "=r"(u) : "f"(x));
    return __uint_as_float(u);
}
__device__ __forceinline__ uint32_t s2u(const void* p) {
    uint32_t a;
    asm("{ .reg .u64 t; cvta.to.shared.u64 t, %1; cvt.u32.u64 %0, t; }"
        : "=r"(a) : "l"(p));
    return a;
}
__device__ __forceinline__ void cpa16(uint32_t dst, const void* src) {
    asm volatile("cp.async.cg.shared.global [%0], [%1], 16;"
                 :: "r"(dst), "l"(src));
}
__device__ __forceinline__ void mma_tf32(float c[4], const uint32_t a[4],
                                         const uint32_t b[2]) {
    asm volatile(
        "mma.sync.aligned.m16n8k8.row.col.f32.tf32.tf32.f32 "
        "{%0,%1,%2,%3},{%4,%5,%6,%7},{%8,%9},{%0,%1,%2,%3};"
        : "+f"(c[0]), "+f"(c[1]), "+f"(c[2]), "+f"(c[3])
        : "r"(a[0]), "r"(a[1]), "r"(a[2]), "r"(a[3]), "r"(b[0]), "r"(b[1]));
}

// ---------------------------------------------------------------------------
// prepasses: tf32 rounding (RNA) of activations and weights
// ---------------------------------------------------------------------------
__global__ __launch_bounds__(256) void round_val(const float* __restrict__ val)
{
    size_t i = ((size_t)blockIdx.x * 256 + threadIdx.x) * 4;
    float4 v = *(const float4*)(val + i);
    v.x = tf32f(v.x); v.y = tf32f(v.y); v.z = tf32f(v.z); v.w = tf32f(v.w);
    *(float4*)(g_ar + i) = v;
}

__global__ __launch_bounds__(256) void round_w(
    const float* __restrict__ Wq, const float* __restrict__ Wk,
    const float* __restrict__ Wv)
{
    const int z = blockIdx.y;
    const float* W = (z == 0) ? Wq : (z == 1) ? Wk : Wv;
    size_t i = ((size_t)blockIdx.x * 256 + threadIdx.x) * 4;
    float4 v = *(const float4*)(W + i);
    v.x = tf32f(v.x); v.y = tf32f(v.y); v.z = tf32f(v.z); v.w = tf32f(v.w);
    *(float4*)(g_w3 + (size_t)z * DMODEL * DMODEL + i) = v;
}

// ---------------------------------------------------------------------------
// Kernel 1: QKV projection, legacy mma.sync tf32, cp.async 3-stage pipeline.
// R11: 512 threads / 16 warps (4 per SMSP) to hide the ~30cyc legacy-mma
// latency. CTA tile 256x128, warp tile 64x32 (4m x 4n warps). Same smem
// layout as the proven R5 kernel (A [256][36], B [32][136]).
// ---------------------------------------------------------------------------
#define GM 256
#define GN 128
#define KC 32
#define NST (DMODEL / KC)             // 24
#define ASTR 36
#define BSTR 136
#define AWORDS (GM * ASTR)            // 9216
#define STWORDS (AWORDS + KC * BSTR)  // 13568
#define SMEM_G (3 * STWORDS * 4)      // 162816 bytes

__global__ __launch_bounds__(512, 1) void qkv_gemm(
    const float* __restrict__ bq, const float* __restrict__ bk,
    const float* __restrict__ bv)
{
    extern __shared__ __align__(16) float smem[];
    const uint32_t sb = s2u(smem);

    const int tid  = threadIdx.x;
    const int lane = tid & 31;
    const int w    = tid >> 5;
    const int wm   = (w & 3) * 64;    // 4 m-warps
    const int wn   = (w >> 2) * 32;   // 4 n-warps
    const int qd   = lane >> 2;       // 0..7
    const int kl   = lane & 3;        // 0..3

    const int z = blockIdx.z;
    const float* __restrict__ Wt   = g_w3 + (size_t)z * DMODEL * DMODEL;
    const float* __restrict__ bias = (z == 0) ? bq : (z == 1) ? bk : bv;
    float* outp = (z == 0) ? g_q : (z == 1) ? g_k : g_v;
    const float scale = (z == 0) ? 0.125f : 1.0f;
    const int bm = blockIdx.y * GM;
    const int bn = blockIdx.x * GN;

    float acc[4][4][4];
#pragma unroll
    for (int mt = 0; mt < 4; mt++)
#pragma unroll
        for (int nt = 0; nt < 4; nt++)
#pragma unroll
            for (int i = 0; i < 4; i++) acc[mt][nt][i] = 0.f;

    auto load_stage = [&](int s) {
        const uint32_t base = sb + (uint32_t)(s % 3) * (STWORDS * 4);
        const int k0 = s * KC;
        // A: 2048 16B-chunks over 512 threads
#pragma unroll
        for (int i = 0; i < 4; i++) {
            const int c  = tid + 512 * i;
            const int m  = c >> 3;
            const int k4 = (c & 7) * 4;
            cpa16(base + (uint32_t)(m * ASTR + k4) * 4,
                  g_ar + (size_t)(bm + m) * DMODEL + k0 + k4);
        }
        // B: 1024 chunks over 512 threads
#pragma unroll
        for (int i = 0; i < 2; i++) {
            const int c  = tid + 512 * i;
            const int kr = c >> 5;
            const int n4 = (c & 31) * 4;
            cpa16(base + (uint32_t)(AWORDS + kr * BSTR + n4) * 4,
                  Wt + (size_t)(k0 + kr) * DMODEL + bn + n4);
        }
        asm volatile("cp.async.commit_group;" ::: "memory");
    };

    load_stage(0); load_stage(1); load_stage(2);

    for (int s = 0; s < NST; s++) {
        asm volatile("cp.async.wait_group 2;" ::: "memory");
        __syncthreads();

        const float* As = smem + (s % 3) * STWORDS;
        const float* Bs = As + AWORDS;

#pragma unroll
        for (int ks = 0; ks < 4; ks++) {
            const int kc = ks * 8 + kl;
            uint32_t af[4][4];
#pragma unroll
            for (int mt = 0; mt < 4; mt++) {
                const int r = wm + mt * 16 + qd;
                af[mt][0] = __float_as_uint(As[r * ASTR + kc]);
                af[mt][1] = __float_as_uint(As[(r + 8) * ASTR + kc]);
                af[mt][2] = __float_as_uint(As[r * ASTR + kc + 4]);
                af[mt][3] = __float_as_uint(As[(r + 8) * ASTR + kc + 4]);
            }
            uint32_t bf[4][2];
#pragma unroll
            for (int nt = 0; nt < 4; nt++) {
                const int cc = wn + nt * 8 + qd;
                bf[nt][0] = __float_as_uint(Bs[kc * BSTR + cc]);
                bf[nt][1] = __float_as_uint(Bs[(kc + 4) * BSTR + cc]);
            }
#pragma unroll
            for (int mt = 0; mt < 4; mt++)
#pragma unroll
                for (int nt = 0; nt < 4; nt++)
                    mma_tf32(acc[mt][nt], af[mt], bf[nt]);
        }

        __syncthreads();
        if (s + 3 < NST) load_stage(s + 3);
        else asm volatile("cp.async.commit_group;" ::: "memory");  // keep count
    }

    // epilogue: bias + scale, RNA-round to tf32, 8B stores
#pragma unroll
    for (int mt = 0; mt < 4; mt++) {
        const int row0 = bm + wm + mt * 16 + qd;
#pragma unroll
        for (int nt = 0; nt < 4; nt++) {
            const int col = bn + wn + nt * 8 + 2 * kl;
            const float2 b2 = *(const float2*)(bias + col);
            float2 o0, o1;
            o0.x = tf32f((acc[mt][nt][0] + b2.x) * scale);
            o0.y = tf32f((acc[mt][nt][1] + b2.y) * scale);
            o1.x = tf32f((acc[mt][nt][2] + b2.x) * scale);
            o1.y = tf32f((acc[mt][nt][3] + b2.y) * scale);
            *(float2*)(outp + (size_t)row0 * DMODEL + col)       = o0;
            *(float2*)(outp + (size_t)(row0 + 8) * DMODEL + col) = o1;
        }
    }
}

// ---------------------------------------------------------------------------
// Kernel 2: flash-style causal sliding-window attention on tensor cores.
// R11: P is staged into the RETIRING K buffer (dead between S=QK^T and
// load_chunk(u+2); 4*PWORDS == KWORDS exactly) behind a new __syncthreads.
// smem 89KB -> 71.7KB => 3 CTAs/SM (3 warps/SMSP) for latency hiding.
// ---------------------------------------------------------------------------
#define KWORDS 4352            // 64*68
#define VWORDS 4608            // 64*72
#define PWORDS 1088            // 16*68  (4 warps * PWORDS == KWORDS)
#define SMEM_A ((2*KWORDS + 2*VWORDS) * 4)   // 71680 bytes

__global__ __launch_bounds__(128) void attn_mma(float* __restrict__ out)
{
    extern __shared__ __align__(16) float sm[];
    const uint32_t smb = s2u(sm);

    const int tid  = threadIdx.x;
    const int lane = tid & 31;
    const int wid  = tid >> 5;
    const int h    = blockIdx.y;
    const int b    = blockIdx.z;
    const int q0   = blockIdx.x * 64;
    const int r    = lane >> 2;     // mma group id
    const int c    = lane & 3;      // mma thread-in-group
    const int qa   = q0 + wid * 16 + r;          // absolute query (and +8)

    // Q fragments (values already tf32-rounded by the GEMM epilogue)
    uint32_t aq[8][4];
    {
        const float* q_lo = g_q + ((size_t)qa * BATCH + b) * DMODEL + h * HDIM;
        const float* q_hi = q_lo + (size_t)8 * BATCH * DMODEL;
#pragma unroll
        for (int kt = 0; kt < 8; kt++) {
            aq[kt][0] = __float_as_uint(q_lo[kt * 8 + c]);
            aq[kt][1] = __float_as_uint(q_hi[kt * 8 + c]);
            aq[kt][2] = __float_as_uint(q_lo[kt * 8 + c + 4]);
            aq[kt][3] = __float_as_uint(q_hi[kt * 8 + c + 4]);
        }
    }

    float oacc[8][4];
#pragma unroll
    for (int nt = 0; nt < 8; nt++)
#pragma unroll
        for (int i = 0; i < 4; i++) oacc[nt][i] = 0.f;
    float m0 = -1e30f, m1 = -1e30f, l0 = 0.f, l1 = 0.f;

    const int t_start = (q0 >= WSZ) ? 0 : ((WSZ - q0) >> 6);
    const int nch     = 5 - t_start;
    const int kbase0  = q0 - WSZ + t_start * 64;   // >= 0, 64-aligned

    auto load_chunk = [&](int u) {
        const int cb = kbase0 + u * 64;
        const uint32_t kd = smb + (uint32_t)((u & 1) * KWORDS) * 4;
        const uint32_t vd = smb + (uint32_t)(2 * KWORDS + (u & 1) * VWORDS) * 4;
        const size_t gb = ((size_t)cb * BATCH + b) * DMODEL + h * HDIM;
#pragma unroll
        for (int it = 0; it < 8; it++) {
            const int f   = tid + 128 * it;
            const int row = f >> 4;
            const int ch  = (f & 15) * 4;
            const size_t g = gb + (size_t)row * (BATCH * DMODEL) + ch;
            cpa16(kd + (uint32_t)(row * 68 + ch) * 4, g_k + g);
            cpa16(vd + (uint32_t)(row * 72 + ch) * 4, g_v + g);
        }
        asm volatile("cp.async.commit_group;" ::: "memory");
    };

    load_chunk(0);
    if (nch > 1) load_chunk(1);
    else asm volatile("cp.async.commit_group;" ::: "memory");

    const float NEGINF = __int_as_float(0xff800000);

    for (int u = 0; u < nch; u++) {
        asm volatile("cp.async.wait_group 1;" ::: "memory");
        __syncthreads();

        const float* Kb = sm + (u & 1) * KWORDS;
        const float* Vb = sm + 2 * KWORDS + (u & 1) * VWORDS;
        float* Pw = sm + (u & 1) * KWORDS + wid * PWORDS;   // alias into Kb
        const int cb = kbase0 + u * 64;

        // ---- S = Q K^T ----
        float sacc[8][4];
#pragma unroll
        for (int nt = 0; nt < 8; nt++)
#pragma unroll
            for (int i = 0; i < 4; i++) sacc[nt][i] = 0.f;
#pragma unroll
        for (int kt = 0; kt < 8; kt++) {
#pragma unroll
            for (int nt = 0; nt < 8; nt++) {
                uint32_t bf[2];
                const float* kp = Kb + (8 * nt + r) * 68 + 8 * kt + c;
                bf[0] = __float_as_uint(kp[0]);
                bf[1] = __float_as_uint(kp[4]);
                mma_tf32(sacc[nt], aq[kt], bf);
            }
        }

        // ---- mask + rowmax (registers only) ----
        float rmax0 = NEGINF, rmax1 = NEGINF;
#pragma unroll
        for (int nt = 0; nt < 8; nt++) {
            const int j = cb + 8 * nt + 2 * c;
            sacc[nt][0] = ((unsigned)(qa - j)         <= WSZ) ? sacc[nt][0] : NEGINF;
            sacc[nt][1] = ((unsigned)(qa - j - 1)     <= WSZ) ? sacc[nt][1] : NEGINF;
            sacc[nt][2] = ((unsigned)(qa + 8 - j)     <= WSZ) ? sacc[nt][2] : NEGINF;
            sacc[nt][3] = ((unsigned)(qa + 8 - j - 1) <= WSZ) ? sacc[nt][3] : NEGINF;
            rmax0 = fmaxf(rmax0, fmaxf(sacc[nt][0], sacc[nt][1]));
            rmax1 = fmaxf(rmax1, fmaxf(sacc[nt][2], sacc[nt][3]));
        }
        rmax0 = fmaxf(rmax0, __shfl_xor_sync(0xffffffffu, rmax0, 1));
        rmax0 = fmaxf(rmax0, __shfl_xor_sync(0xffffffffu, rmax0, 2));
        rmax1 = fmaxf(rmax1, __shfl_xor_sync(0xffffffffu, rmax1, 1));
        rmax1 = fmaxf(rmax1, __shfl_xor_sync(0xffffffffu, rmax1, 2));

        const float mn0 = fmaxf(m0, rmax0), mn1 = fmaxf(m1, rmax1);
        const float f0 = __expf(m0 - mn0), f1 = __expf(m1 - mn1);
        m0 = mn0; m1 = mn1;

        // all warps must be done reading Kb before P overwrites it
        __syncthreads();

        // ---- exp, rowsum, P -> smem (RNA-rounded, into retired K space) ----
        float rs0 = 0.f, rs1 = 0.f;
#pragma unroll
        for (int nt = 0; nt < 8; nt++) {
            const float p00 = __expf(sacc[nt][0] - m0);
            const float p01 = __expf(sacc[nt][1] - m0);
            const float p10 = __expf(sacc[nt][2] - m1);
            const float p11 = __expf(sacc[nt][3] - m1);
            rs0 += p00 + p01;
            rs1 += p10 + p11;
            *(float2*)&Pw[r * 68 + 8 * nt + 2 * c] =
                make_float2(tf32f(p00), tf32f(p01));
            *(float2*)&Pw[(r + 8) * 68 + 8 * nt + 2 * c] =
                make_float2(tf32f(p10), tf32f(p11));
        }
        rs0 += __shfl_xor_sync(0xffffffffu, rs0, 1);
        rs0 += __shfl_xor_sync(0xffffffffu, rs0, 2);
        rs1 += __shfl_xor_sync(0xffffffffu, rs1, 1);
        rs1 += __shfl_xor_sync(0xffffffffu, rs1, 2);
        l0 = l0 * f0 + rs0;
        l1 = l1 * f1 + rs1;
#pragma unroll
        for (int nt = 0; nt < 8; nt++) {
            oacc[nt][0] *= f0; oacc[nt][1] *= f0;
            oacc[nt][2] *= f1; oacc[nt][3] *= f1;
        }
        __syncwarp();   // P store -> P load visibility within warp

        // ---- O += P V ----
#pragma unroll
        for (int kt = 0; kt < 8; kt++) {
            uint32_t ap[4];
            ap[0] = __float_as_uint(Pw[r * 68 + 8 * kt + c]);
            ap[1] = __float_as_uint(Pw[(r + 8) * 68 + 8 * kt + c]);
            ap[2] = __float_as_uint(Pw[r * 68 + 8 * kt + c + 4]);
            ap[3] = __float_as_uint(Pw[(r + 8) * 68 + 8 * kt + c + 4]);
#pragma unroll
            for (int nt = 0; nt < 8; nt++) {
                uint32_t bf[2];
                const float* vp = Vb + (8 * kt + c) * 72 + 8 * nt + r;
                bf[0] = __float_as_uint(vp[0]);
                bf[1] = __float_as_uint(vp[4 * 72]);
                mma_tf32(oacc[nt], ap, bf);
            }
        }

        __syncthreads();
        if (u + 2 < nch) load_chunk(u + 2);
        else asm volatile("cp.async.commit_group;" ::: "memory");
    }

    // ---- epilogue ----
    const float i0 = 1.f / l0, i1 = 1.f / l1;
    float* o_lo = out + ((size_t)qa * BATCH + b) * DMODEL + h * HDIM;
    float* o_hi = o_lo + (size_t)8 * BATCH * DMODEL;
#pragma unroll
    for (int nt = 0; nt < 8; nt++) {
        *(float2*)&o_lo[8 * nt + 2 * c] =
            make_float2(oacc[nt][0] * i0, oacc[nt][1] * i0);
        *(float2*)&o_hi[8 * nt + 2 * c] =
            make_float2(oacc[nt][2] * i1, oacc[nt][3] * i1);
    }
}

// ---------------------------------------------------------------------------
extern "C" void kernel_launch(void* const* d_in, const int* in_sizes, int n_in,
                              void* d_out, int out_size)
{
    const float* val = (const float*)d_in[0];
    const float* Wq  = (const float*)d_in[1];
    const float* bq  = (const float*)d_in[2];
    const float* Wk  = (const float*)d_in[3];
    const float* bk  = (const float*)d_in[4];
    const float* Wv  = (const float*)d_in[5];
    const float* bv  = (const float*)d_in[6];
    float* out = (float*)d_out;

    cudaFuncSetAttribute(qkv_gemm,
                         cudaFuncAttributeMaxDynamicSharedMemorySize, SMEM_G);
    cudaFuncSetAttribute(attn_mma,
                         cudaFuncAttributeMaxDynamicSharedMemorySize, SMEM_A);

    round_val<<<(size_t)NROWS * DMODEL / 1024, 256>>>(val);
    round_w<<<dim3(DMODEL * DMODEL / 1024, 3), 256>>>(Wq, Wk, Wv);

    dim3 g1(DMODEL / GN, NROWS / GM, 3);    // 6 x 32 x 3
    qkv_gemm<<<g1, 512, SMEM_G>>>(bq, bk, bv);

    dim3 g2(S_LEN / 64, NHEAD, BATCH);      // 64 x 12 x 2
    attn_mma<<<g2, 128, SMEM_A>>>(out);
}

// round 12
// speedup vs baseline: 1.3776x; 1.3776x over previous
#include <cuda_runtime.h>
#include <cuda_fp16.h>
#include <cstdint>

#define S_LEN  4096
#define BATCH  2
#define DMODEL 768
#define NHEAD  12
#define HDIM   64
#define WSZ    256
#define NROWS  (S_LEN * BATCH)   // 8192

// scratch (device globals: allowed, no allocation)
__device__ float  g_q [(size_t)NROWS * DMODEL];
__device__ float  g_k [(size_t)NROWS * DMODEL];
__device__ float  g_v [(size_t)NROWS * DMODEL];
__device__ __half g_ah[(size_t)NROWS * DMODEL];        // fp16 activations
__device__ __half g_wh[(size_t)3 * DMODEL * DMODEL];   // fp16 W^T: [z][n][k]

// ---------------------------------------------------------------------------
// helpers
// ---------------------------------------------------------------------------
__device__ __forceinline__ float tf32f(float x) {
    uint32_t u;
    asm("cvt.rna.tf32.f32 %0,%1;" : "=r"(u) : "f"(x));
    return __uint_as_float(u);
}
__device__ __forceinline__ uint32_t s2u(const void* p) {
    uint32_t a;
    asm("{ .reg .u64 t; cvta.to.shared.u64 t, %1; cvt.u32.u64 %0, t; }"
        : "=r"(a) : "l"(p));
    return a;
}
__device__ __forceinline__ void cpa16(uint32_t dst, const void* src) {
    asm volatile("cp.async.cg.shared.global [%0], [%1], 16;"
                 :: "r"(dst), "l"(src));
}
__device__ __forceinline__ void mma_tf32(float c[4], const uint32_t a[4],
                                         const uint32_t b[2]) {
    asm volatile(
        "mma.sync.aligned.m16n8k8.row.col.f32.tf32.tf32.f32 "
        "{%0,%1,%2,%3},{%4,%5,%6,%7},{%8,%9},{%0,%1,%2,%3};"
        : "+f"(c[0]), "+f"(c[1]), "+f"(c[2]), "+f"(c[3])
        : "r"(a[0]), "r"(a[1]), "r"(a[2]), "r"(a[3]), "r"(b[0]), "r"(b[1]));
}
__device__ __forceinline__ void mma_f16(float c[4], const uint32_t a[4],
                                        const uint32_t b[2]) {
    asm volatile(
        "mma.sync.aligned.m16n8k16.row.col.f32.f16.f16.f32 "
        "{%0,%1,%2,%3},{%4,%5,%6,%7},{%8,%9},{%0,%1,%2,%3};"
        : "+f"(c[0]), "+f"(c[1]), "+f"(c[2]), "+f"(c[3])
        : "r"(a[0]), "r"(a[1]), "r"(a[2]), "r"(a[3]), "r"(b[0]), "r"(b[1]));
}

// ---------------------------------------------------------------------------
// prepasses: fp16 (RN) conversion of activations; transpose+convert of W
// ---------------------------------------------------------------------------
__global__ __launch_bounds__(256) void conv_val(const float* __restrict__ val)
{
    size_t i = ((size_t)blockIdx.x * 256 + threadIdx.x) * 4;
    float4 v = *(const float4*)(val + i);
    __half2 h0 = __floats2half2_rn(v.x, v.y);
    __half2 h1 = __floats2half2_rn(v.z, v.w);
    *(__half2*)(g_ah + i)     = h0;
    *(__half2*)(g_ah + i + 2) = h1;
}

// g_wh[z][n][k] = (half) W[z][k][n]
__global__ __launch_bounds__(256) void conv_w(
    const float* __restrict__ Wq, const float* __restrict__ Wk,
    const float* __restrict__ Wv)
{
    __shared__ float tile[32][33];
    const int z = blockIdx.z;
    const float* W = (z == 0) ? Wq : (z == 1) ? Wk : Wv;
    __half* out = g_wh + (size_t)z * DMODEL * DMODEL;
    const int k0 = blockIdx.y * 32, n0 = blockIdx.x * 32;
    const int tx = threadIdx.x & 31, ty = threadIdx.x >> 5;   // (32,8)
#pragma unroll
    for (int r = 0; r < 4; r++)
        tile[ty + 8 * r][tx] = W[(size_t)(k0 + ty + 8 * r) * DMODEL + n0 + tx];
    __syncthreads();
#pragma unroll
    for (int r = 0; r < 4; r++)
        out[(size_t)(n0 + ty + 8 * r) * DMODEL + k0 + tx] =
            __float2half_rn(tile[tx][ty + 8 * r]);
}

// ---------------------------------------------------------------------------
// Kernel 1: QKV projection, fp16 mma.sync (m16n8k16), cp.async 3-stage
// pipeline.  256 threads, 8 warps (4m x 2n), warp tile 64x64, KC=32 fp16.
//   A smem: [256 rows][20 words] (40 fp16, 8 pad)   — frag words qd*20+c: 32 banks
//   B smem: [128 n-rows][20 words] (W^T, k contiguous) — same stride, clean
// ---------------------------------------------------------------------------
#define GM 256
#define GN 128
#define KC 32                          // fp16 k per stage (2 mma k-steps)
#define NST (DMODEL / KC)              // 24
#define AST2 20                        // A row stride in 32-bit words
#define BST2 20
#define AW32 (GM * AST2)               // 5120 words
#define BW32 (GN * BST2)               // 2560 words
#define STW  (AW32 + BW32)             // 7680 words
#define SMEM_G (3 * STW * 4)           // 92160 bytes

__global__ __launch_bounds__(256, 1) void qkv_gemm(
    const float* __restrict__ bq, const float* __restrict__ bk,
    const float* __restrict__ bv)
{
    extern __shared__ __align__(16) uint32_t smem[];
    const uint32_t sb = s2u(smem);

    const int tid  = threadIdx.x;
    const int lane = tid & 31;
    const int w    = tid >> 5;
    const int wm   = (w & 3) * 64;
    const int wn   = (w >> 2) * 64;
    const int qd   = lane >> 2;      // 0..7
    const int kl   = lane & 3;       // 0..3

    const int z = blockIdx.z;
    const __half* __restrict__ Wt  = g_wh + (size_t)z * DMODEL * DMODEL;
    const float* __restrict__ bias = (z == 0) ? bq : (z == 1) ? bk : bv;
    float* outp = (z == 0) ? g_q : (z == 1) ? g_k : g_v;
    const float scale = (z == 0) ? 0.125f : 1.0f;
    const int bm = blockIdx.y * GM;
    const int bn = blockIdx.x * GN;

    float acc[4][8][4];
#pragma unroll
    for (int mt = 0; mt < 4; mt++)
#pragma unroll
        for (int nt = 0; nt < 8; nt++)
#pragma unroll
            for (int i = 0; i < 4; i++) acc[mt][nt][i] = 0.f;

    auto load_stage = [&](int s) {
        const uint32_t base = sb + (uint32_t)(s % 3) * (STW * 4);
        const int k0 = s * KC;
        // A: 256 rows x 4 chunks (16B = 8 fp16) = 1024 chunks
#pragma unroll
        for (int i = 0; i < 4; i++) {
            const int c = tid + 256 * i;
            const int m = c >> 2;
            const int j = c & 3;
            cpa16(base + (uint32_t)(m * AST2 + j * 4) * 4,
                  g_ah + (size_t)(bm + m) * DMODEL + k0 + j * 8);
        }
        // B (W^T): 128 rows x 4 chunks = 512 chunks
#pragma unroll
        for (int i = 0; i < 2; i++) {
            const int c = tid + 256 * i;
            const int n = c >> 2;
            const int j = c & 3;
            cpa16(base + (uint32_t)(AW32 + n * BST2 + j * 4) * 4,
                  Wt + (size_t)(bn + n) * DMODEL + k0 + j * 8);
        }
        asm volatile("cp.async.commit_group;" ::: "memory");
    };

    load_stage(0); load_stage(1); load_stage(2);

    for (int s = 0; s < NST; s++) {
        asm volatile("cp.async.wait_group 2;" ::: "memory");
        __syncthreads();

        const uint32_t* As = smem + (s % 3) * STW;
        const uint32_t* Bs = As + AW32;

#pragma unroll
        for (int ks = 0; ks < 2; ks++) {
            const int kw = ks * 8 + kl;
            uint32_t af[4][4];
#pragma unroll
            for (int mt = 0; mt < 4; mt++) {
                const int r = wm + mt * 16 + qd;
                af[mt][0] = As[r * AST2 + kw];
                af[mt][1] = As[(r + 8) * AST2 + kw];
                af[mt][2] = As[r * AST2 + kw + 4];
                af[mt][3] = As[(r + 8) * AST2 + kw + 4];
            }
            uint32_t bf[8][2];
#pragma unroll
            for (int nt = 0; nt < 8; nt++) {
                const int cc = wn + nt * 8 + qd;
                bf[nt][0] = Bs[cc * BST2 + kw];
                bf[nt][1] = Bs[cc * BST2 + kw + 4];
            }
#pragma unroll
            for (int mt = 0; mt < 4; mt++)
#pragma unroll
                for (int nt = 0; nt < 8; nt++)
                    mma_f16(acc[mt][nt], af[mt], bf[nt]);
        }

        __syncthreads();
        if (s + 3 < NST) load_stage(s + 3);
        else asm volatile("cp.async.commit_group;" ::: "memory");  // keep count
    }

    // epilogue: bias + scale, RNA-round to tf32 (attention consumes tf32)
#pragma unroll
    for (int mt = 0; mt < 4; mt++) {
        const int row0 = bm + wm + mt * 16 + qd;
#pragma unroll
        for (int nt = 0; nt < 8; nt++) {
            const int col = bn + wn + nt * 8 + 2 * kl;
            const float2 b2 = *(const float2*)(bias + col);
            float2 o0, o1;
            o0.x = tf32f((acc[mt][nt][0] + b2.x) * scale);
            o0.y = tf32f((acc[mt][nt][1] + b2.y) * scale);
            o1.x = tf32f((acc[mt][nt][2] + b2.x) * scale);
            o1.y = tf32f((acc[mt][nt][3] + b2.y) * scale);
            *(float2*)(outp + (size_t)row0 * DMODEL + col)       = o0;
            *(float2*)(outp + (size_t)(row0 + 8) * DMODEL + col) = o1;
        }
    }
}

// ---------------------------------------------------------------------------
// Kernel 2: flash-style causal sliding-window attention on tensor cores.
// (verbatim from R11 run: 82.2 us; P staged into retiring K buffer,
//  smem 71.7KB -> 3 CTAs/SM)
// ---------------------------------------------------------------------------
#define KWORDS 4352            // 64*68
#define VWORDS 4608            // 64*72
#define PWORDS 1088            // 16*68  (4 warps * PWORDS == KWORDS)
#define SMEM_A ((2*KWORDS + 2*VWORDS) * 4)   // 71680 bytes

__global__ __launch_bounds__(128) void attn_mma(float* __restrict__ out)
{
    extern __shared__ __align__(16) float sm[];
    const uint32_t smb = s2u(sm);

    const int tid  = threadIdx.x;
    const int lane = tid & 31;
    const int wid  = tid >> 5;
    const int h    = blockIdx.y;
    const int b    = blockIdx.z;
    const int q0   = blockIdx.x * 64;
    const int r    = lane >> 2;     // mma group id
    const int c    = lane & 3;      // mma thread-in-group
    const int qa   = q0 + wid * 16 + r;          // absolute query (and +8)

    // Q fragments (values already tf32-rounded by the GEMM epilogue)
    uint32_t aq[8][4];
    {
        const float* q_lo = g_q + ((size_t)qa * BATCH + b) * DMODEL + h * HDIM;
        const float* q_hi = q_lo + (size_t)8 * BATCH * DMODEL;
#pragma unroll
        for (int kt = 0; kt < 8; kt++) {
            aq[kt][0] = __float_as_uint(q_lo[kt * 8 + c]);
            aq[kt][1] = __float_as_uint(q_hi[kt * 8 + c]);
            aq[kt][2] = __float_as_uint(q_lo[kt * 8 + c + 4]);
            aq[kt][3] = __float_as_uint(q_hi[kt * 8 + c + 4]);
        }
    }

    float oacc[8][4];
#pragma unroll
    for (int nt = 0; nt < 8; nt++)
#pragma unroll
        for (int i = 0; i < 4; i++) oacc[nt][i] = 0.f;
    float m0 = -1e30f, m1 = -1e30f, l0 = 0.f, l1 = 0.f;

    const int t_start = (q0 >= WSZ) ? 0 : ((WSZ - q0) >> 6);
    const int nch     = 5 - t_start;
    const int kbase0  = q0 - WSZ + t_start * 64;   // >= 0, 64-aligned

    auto load_chunk = [&](int u) {
        const int cb = kbase0 + u * 64;
        const uint32_t kd = smb + (uint32_t)((u & 1) * KWORDS) * 4;
        const uint32_t vd = smb + (uint32_t)(2 * KWORDS + (u & 1) * VWORDS) * 4;
        const size_t gb = ((size_t)cb * BATCH + b) * DMODEL + h * HDIM;
#pragma unroll
        for (int it = 0; it < 8; it++) {
            const int f   = tid + 128 * it;
            const int row = f >> 4;
            const int ch  = (f & 15) * 4;
            const size_t g = gb + (size_t)row * (BATCH * DMODEL) + ch;
            cpa16(kd + (uint32_t)(row * 68 + ch) * 4, g_k + g);
            cpa16(vd + (uint32_t)(row * 72 + ch) * 4, g_v + g);
        }
        asm volatile("cp.async.commit_group;" ::: "memory");
    };

    load_chunk(0);
    if (nch > 1) load_chunk(1);
    else asm volatile("cp.async.commit_group;" ::: "memory");

    const float NEGINF = __int_as_float(0xff800000);

    for (int u = 0; u < nch; u++) {
        asm volatile("cp.async.wait_group 1;" ::: "memory");
        __syncthreads();

        const float* Kb = sm + (u & 1) * KWORDS;
        const float* Vb = sm + 2 * KWORDS + (u & 1) * VWORDS;
        float* Pw = sm + (u & 1) * KWORDS + wid * PWORDS;   // alias into Kb
        const int cb = kbase0 + u * 64;

        // ---- S = Q K^T ----
        float sacc[8][4];
#pragma unroll
        for (int nt = 0; nt < 8; nt++)
#pragma unroll
            for (int i = 0; i < 4; i++) sacc[nt][i] = 0.f;
#pragma unroll
        for (int kt = 0; kt < 8; kt++) {
#pragma unroll
            for (int nt = 0; nt < 8; nt++) {
                uint32_t bf[2];
                const float* kp = Kb + (8 * nt + r) * 68 + 8 * kt + c;
                bf[0] = __float_as_uint(kp[0]);
                bf[1] = __float_as_uint(kp[4]);
                mma_tf32(sacc[nt], aq[kt], bf);
            }
        }

        // ---- mask + rowmax (registers only) ----
        float rmax0 = NEGINF, rmax1 = NEGINF;
#pragma unroll
        for (int nt = 0; nt < 8; nt++) {
            const int j = cb + 8 * nt + 2 * c;
            sacc[nt][0] = ((unsigned)(qa - j)         <= WSZ) ? sacc[nt][0] : NEGINF;
            sacc[nt][1] = ((unsigned)(qa - j - 1)     <= WSZ) ? sacc[nt][1] : NEGINF;
            sacc[nt][2] = ((unsigned)(qa + 8 - j)     <= WSZ) ? sacc[nt][2] : NEGINF;
            sacc[nt][3] = ((unsigned)(qa + 8 - j - 1) <= WSZ) ? sacc[nt][3] : NEGINF;
            rmax0 = fmaxf(rmax0, fmaxf(sacc[nt][0], sacc[nt][1]));
            rmax1 = fmaxf(rmax1, fmaxf(sacc[nt][2], sacc[nt][3]));
        }
        rmax0 = fmaxf(rmax0, __shfl_xor_sync(0xffffffffu, rmax0, 1));
        rmax0 = fmaxf(rmax0, __shfl_xor_sync(0xffffffffu, rmax0, 2));
        rmax1 = fmaxf(rmax1, __shfl_xor_sync(0xffffffffu, rmax1, 1));
        rmax1 = fmaxf(rmax1, __shfl_xor_sync(0xffffffffu, rmax1, 2));

        const float mn0 = fmaxf(m0, rmax0), mn1 = fmaxf(m1, rmax1);
        const float f0 = __expf(m0 - mn0), f1 = __expf(m1 - mn1);
        m0 = mn0; m1 = mn1;

        // all warps must be done reading Kb before P overwrites it
        __syncthreads();

        // ---- exp, rowsum, P -> smem (RNA-rounded, into retired K space) ----
        float rs0 = 0.f, rs1 = 0.f;
#pragma unroll
        for (int nt = 0; nt < 8; nt++) {
            const float p00 = __expf(sacc[nt][0] - m0);
            const float p01 = __expf(sacc[nt][1] - m0);
            const float p10 = __expf(sacc[nt][2] - m1);
            const float p11 = __expf(sacc[nt][3] - m1);
            rs0 += p00 + p01;
            rs1 += p10 + p11;
            *(float2*)&Pw[r * 68 + 8 * nt + 2 * c] =
                make_float2(tf32f(p00), tf32f(p01));
            *(float2*)&Pw[(r + 8) * 68 + 8 * nt + 2 * c] =
                make_float2(tf32f(p10), tf32f(p11));
        }
        rs0 += __shfl_xor_sync(0xffffffffu, rs0, 1);
        rs0 += __shfl_xor_sync(0xffffffffu, rs0, 2);
        rs1 += __shfl_xor_sync(0xffffffffu, rs1, 1);
        rs1 += __shfl_xor_sync(0xffffffffu, rs1, 2);
        l0 = l0 * f0 + rs0;
        l1 = l1 * f1 + rs1;
#pragma unroll
        for (int nt = 0; nt < 8; nt++) {
            oacc[nt][0] *= f0; oacc[nt][1] *= f0;
            oacc[nt][2] *= f1; oacc[nt][3] *= f1;
        }
        __syncwarp();   // P store -> P load visibility within warp

        // ---- O += P V ----
#pragma unroll
        for (int kt = 0; kt < 8; kt++) {
            uint32_t ap[4];
            ap[0] = __float_as_uint(Pw[r * 68 + 8 * kt + c]);
            ap[1] = __float_as_uint(Pw[(r + 8) * 68 + 8 * kt + c]);
            ap[2] = __float_as_uint(Pw[r * 68 + 8 * kt + c + 4]);
            ap[3] = __float_as_uint(Pw[(r + 8) * 68 + 8 * kt + c + 4]);
#pragma unroll
            for (int nt = 0; nt < 8; nt++) {
                uint32_t bf[2];
                const float* vp = Vb + (8 * kt + c) * 72 + 8 * nt + r;
                bf[0] = __float_as_uint(vp[0]);
                bf[1] = __float_as_uint(vp[4 * 72]);
                mma_tf32(oacc[nt], ap, bf);
            }
        }

        __syncthreads();
        if (u + 2 < nch) load_chunk(u + 2);
        else asm volatile("cp.async.commit_group;" ::: "memory");
    }

    // ---- epilogue ----
    const float i0 = 1.f / l0, i1 = 1.f / l1;
    float* o_lo = out + ((size_t)qa * BATCH + b) * DMODEL + h * HDIM;
    float* o_hi = o_lo + (size_t)8 * BATCH * DMODEL;
#pragma unroll
    for (int nt = 0; nt < 8; nt++) {
        *(float2*)&o_lo[8 * nt + 2 * c] =
            make_float2(oacc[nt][0] * i0, oacc[nt][1] * i0);
        *(float2*)&o_hi[8 * nt + 2 * c] =
            make_float2(oacc[nt][2] * i1, oacc[nt][3] * i1);
    }
}

// ---------------------------------------------------------------------------
extern "C" void kernel_launch(void* const* d_in, const int* in_sizes, int n_in,
                              void* d_out, int out_size)
{
    const float* val = (const float*)d_in[0];
    const float* Wq  = (const float*)d_in[1];
    const float* bq  = (const float*)d_in[2];
    const float* Wk  = (const float*)d_in[3];
    const float* bk  = (const float*)d_in[4];
    const float* Wv  = (const float*)d_in[5];
    const float* bv  = (const float*)d_in[6];
    float* out = (float*)d_out;

    cudaFuncSetAttribute(qkv_gemm,
                         cudaFuncAttributeMaxDynamicSharedMemorySize, SMEM_G);
    cudaFuncSetAttribute(attn_mma,
                         cudaFuncAttributeMaxDynamicSharedMemorySize, SMEM_A);

    conv_val<<<(size_t)NROWS * DMODEL / 1024, 256>>>(val);
    conv_w<<<dim3(DMODEL / 32, DMODEL / 32, 3), 256>>>(Wq, Wk, Wv);

    dim3 g1(DMODEL / GN, NROWS / GM, 3);    // 6 x 32 x 3
    qkv_gemm<<<g1, 256, SMEM_G>>>(bq, bk, bv);

    dim3 g2(S_LEN / 64, NHEAD, BATCH);      // 64 x 12 x 2
    attn_mma<<<g2, 128, SMEM_A>>>(out);
}

// round 16
// speedup vs baseline: 1.5532x; 1.1275x over previous
#include <cuda_runtime.h>
#include <cuda_fp16.h>
#include <cstdint>

#define S_LEN  4096
#define BATCH  2
#define DMODEL 768
#define NHEAD  12
#define HDIM   64
#define WSZ    256
#define NROWS  (S_LEN * BATCH)   // 8192

// scratch (device globals: allowed, no allocation)
__device__ __half g_ah[(size_t)NROWS * DMODEL];        // fp16 activations
__device__ __half g_wh[(size_t)3 * DMODEL * DMODEL];   // fp16 W^T: [z][n][k]
__device__ __half g_qh[(size_t)NROWS * DMODEL];        // fp16 q (scaled)
__device__ __half g_kh[(size_t)NROWS * DMODEL];        // fp16 k
__device__ __half g_vh[(size_t)NROWS * DMODEL];        // fp16 v [row][dim]
__device__ __half g_vt[(size_t)DMODEL * BATCH * S_LEN];// fp16 v^T [n][b][s]

// ---------------------------------------------------------------------------
// helpers
// ---------------------------------------------------------------------------
__device__ __forceinline__ uint32_t s2u(const void* p) {
    uint32_t a;
    asm("{ .reg .u64 t; cvta.to.shared.u64 t, %1; cvt.u32.u64 %0, t; }"
        : "=r"(a) : "l"(p));
    return a;
}
__device__ __forceinline__ void cpa16(uint32_t dst, const void* src) {
    asm volatile("cp.async.cg.shared.global [%0], [%1], 16;"
                 :: "r"(dst), "l"(src));
}
__device__ __forceinline__ uint32_t h2u(__half2 h) {
    return *reinterpret_cast<uint32_t*>(&h);
}
__device__ __forceinline__ void mma_f16(float c[4], const uint32_t a[4],
                                        const uint32_t b[2]) {
    asm volatile(
        "mma.sync.aligned.m16n8k16.row.col.f32.f16.f16.f32 "
        "{%0,%1,%2,%3},{%4,%5,%6,%7},{%8,%9},{%0,%1,%2,%3};"
        : "+f"(c[0]), "+f"(c[1]), "+f"(c[2]), "+f"(c[3])
        : "r"(a[0]), "r"(a[1]), "r"(a[2]), "r"(a[3]), "r"(b[0]), "r"(b[1]));
}

// ---------------------------------------------------------------------------
// prepasses: fp16 (RN) conversion of activations; transpose+convert of W
// ---------------------------------------------------------------------------
__global__ __launch_bounds__(256) void conv_val(const float* __restrict__ val)
{
    size_t i = ((size_t)blockIdx.x * 256 + threadIdx.x) * 4;
    float4 v = *(const float4*)(val + i);
    *(__half2*)(g_ah + i)     = __floats2half2_rn(v.x, v.y);
    *(__half2*)(g_ah + i + 2) = __floats2half2_rn(v.z, v.w);
}

// g_wh[z][n][k] = (half) W[z][k][n]
__global__ __launch_bounds__(256) void conv_w(
    const float* __restrict__ Wq, const float* __restrict__ Wk,
    const float* __restrict__ Wv)
{
    __shared__ float tile[32][33];
    const int z = blockIdx.z;
    const float* W = (z == 0) ? Wq : (z == 1) ? Wk : Wv;
    __half* out = g_wh + (size_t)z * DMODEL * DMODEL;
    const int k0 = blockIdx.y * 32, n0 = blockIdx.x * 32;
    const int tx = threadIdx.x & 31, ty = threadIdx.x >> 5;
#pragma unroll
    for (int r = 0; r < 4; r++)
        tile[ty + 8 * r][tx] = W[(size_t)(k0 + ty + 8 * r) * DMODEL + n0 + tx];
    __syncthreads();
#pragma unroll
    for (int r = 0; r < 4; r++)
        out[(size_t)(n0 + ty + 8 * r) * DMODEL + k0 + tx] =
            __float2half_rn(tile[tx][ty + 8 * r]);
}

// ---------------------------------------------------------------------------
// V transpose: g_vt[(n*2 + b)*S_LEN + s] = g_vh[(s*2 + b)*DMODEL + n]
// block handles 64 composite rows x 64 dims; 256 threads.
// ---------------------------------------------------------------------------
__global__ __launch_bounds__(256) void transpose_v()
{
    __shared__ __half tile[64][72];
    const int row0 = blockIdx.x * 64;       // composite rows (s*2+b)
    const int n0   = blockIdx.y * 64;
    const int tid  = threadIdx.x;

#pragma unroll
    for (int i = 0; i < 8; i++) {
        const int f = tid + 256 * i;        // 2048 half2 total
        const int r = f >> 5;
        const int j = (f & 31) * 2;
        *(__half2*)&tile[r][j] =
            *(const __half2*)(g_vh + (size_t)(row0 + r) * DMODEL + n0 + j);
    }
    __syncthreads();

    const int n  = tid >> 2;                // 0..63
    const int b  = (tid >> 1) & 1;
    const int hs = (tid & 1) * 16;          // s offset within the 32-run
    uint32_t w[8];
#pragma unroll
    for (int k = 0; k < 8; k++) {
        __half lo = tile[2 * (hs + 2 * k) + b][n];
        __half hi = tile[2 * (hs + 2 * k + 1) + b][n];
        w[k] = h2u(__halves2half2(lo, hi));
    }
    __half* outp = g_vt + ((size_t)(n0 + n) * 2 + b) * S_LEN + row0 / 2 + hs;
    *(uint4*)(outp)     = make_uint4(w[0], w[1], w[2], w[3]);
    *(uint4*)(outp + 8) = make_uint4(w[4], w[5], w[6], w[7]);
}

// ---------------------------------------------------------------------------
// Kernel 1: QKV projection, fp16 mma.sync (m16n8k16), cp.async 3-stage
// pipeline (proven R12 structure).  Epilogue writes fp16 q/k/v.
// ---------------------------------------------------------------------------
#define GM 256
#define GN 128
#define KC 32
#define NST (DMODEL / KC)              // 24
#define AST2 20
#define BST2 20
#define AW32 (GM * AST2)               // 5120 words
#define BW32 (GN * BST2)               // 2560 words
#define STW  (AW32 + BW32)             // 7680 words
#define SMEM_G (3 * STW * 4)           // 92160 bytes

__global__ __launch_bounds__(256, 1) void qkv_gemm(
    const float* __restrict__ bq, const float* __restrict__ bk,
    const float* __restrict__ bv)
{
    extern __shared__ __align__(16) uint32_t smem[];
    const uint32_t sb = s2u(smem);

    const int tid  = threadIdx.x;
    const int lane = tid & 31;
    const int w    = tid >> 5;
    const int wm   = (w & 3) * 64;
    const int wn   = (w >> 2) * 64;
    const int qd   = lane >> 2;
    const int kl   = lane & 3;

    const int z = blockIdx.z;
    const __half* __restrict__ Wt  = g_wh + (size_t)z * DMODEL * DMODEL;
    const float* __restrict__ bias = (z == 0) ? bq : (z == 1) ? bk : bv;
    __half* outp = (z == 0) ? g_qh : (z == 1) ? g_kh : g_vh;
    const float scale = (z == 0) ? 0.125f : 1.0f;
    const int bm = blockIdx.y * GM;
    const int bn = blockIdx.x * GN;

    float acc[4][8][4];
#pragma unroll
    for (int mt = 0; mt < 4; mt++)
#pragma unroll
        for (int nt = 0; nt < 8; nt++)
#pragma unroll
            for (int i = 0; i < 4; i++) acc[mt][nt][i] = 0.f;

    auto load_stage = [&](int s) {
        const uint32_t base = sb + (uint32_t)(s % 3) * (STW * 4);
        const int k0 = s * KC;
#pragma unroll
        for (int i = 0; i < 4; i++) {
            const int c = tid + 256 * i;
            const int m = c >> 2;
            const int j = c & 3;
            cpa16(base + (uint32_t)(m * AST2 + j * 4) * 4,
                  g_ah + (size_t)(bm + m) * DMODEL + k0 + j * 8);
        }
#pragma unroll
        for (int i = 0; i < 2; i++) {
            const int c = tid + 256 * i;
            const int n = c >> 2;
            const int j = c & 3;
            cpa16(base + (uint32_t)(AW32 + n * BST2 + j * 4) * 4,
                  Wt + (size_t)(bn + n) * DMODEL + k0 + j * 8);
        }
        asm volatile("cp.async.commit_group;" ::: "memory");
    };

    load_stage(0); load_stage(1); load_stage(2);

    for (int s = 0; s < NST; s++) {
        asm volatile("cp.async.wait_group 2;" ::: "memory");
        __syncthreads();

        const uint32_t* As = smem + (s % 3) * STW;
        const uint32_t* Bs = As + AW32;

#pragma unroll
        for (int ks = 0; ks < 2; ks++) {
            const int kw = ks * 8 + kl;
            uint32_t af[4][4];
#pragma unroll
            for (int mt = 0; mt < 4; mt++) {
                const int r = wm + mt * 16 + qd;
                af[mt][0] = As[r * AST2 + kw];
                af[mt][1] = As[(r + 8) * AST2 + kw];
                af[mt][2] = As[r * AST2 + kw + 4];
                af[mt][3] = As[(r + 8) * AST2 + kw + 4];
            }
            uint32_t bf[8][2];
#pragma unroll
            for (int nt = 0; nt < 8; nt++) {
                const int cc = wn + nt * 8 + qd;
                bf[nt][0] = Bs[cc * BST2 + kw];
                bf[nt][1] = Bs[cc * BST2 + kw + 4];
            }
#pragma unroll
            for (int mt = 0; mt < 4; mt++)
#pragma unroll
                for (int nt = 0; nt < 8; nt++)
                    mma_f16(acc[mt][nt], af[mt], bf[nt]);
        }

        __syncthreads();
        if (s + 3 < NST) load_stage(s + 3);
        else asm volatile("cp.async.commit_group;" ::: "memory");  // keep count
    }

    // epilogue: bias + scale, round to fp16, half2 stores
#pragma unroll
    for (int mt = 0; mt < 4; mt++) {
        const int row0 = bm + wm + mt * 16 + qd;
#pragma unroll
        for (int nt = 0; nt < 8; nt++) {
            const int col = bn + wn + nt * 8 + 2 * kl;
            const float2 b2 = *(const float2*)(bias + col);
            *(__half2*)(outp + (size_t)row0 * DMODEL + col) =
                __floats2half2_rn((acc[mt][nt][0] + b2.x) * scale,
                                  (acc[mt][nt][1] + b2.y) * scale);
            *(__half2*)(outp + (size_t)(row0 + 8) * DMODEL + col) =
                __floats2half2_rn((acc[mt][nt][2] + b2.x) * scale,
                                  (acc[mt][nt][3] + b2.y) * scale);
        }
    }
}

// ---------------------------------------------------------------------------
// Kernel 2: flash-style sliding-window attention, full fp16 operands.
// Block = 64 queries of one (b,h), 4 warps x 16 queries.
// S = Q K^T and O += P V both m16n8k16 (4 k-steps each per 64-chunk).
// K smem [64 keys][72 halves]; Vt smem [64 dims][72 halves] (from g_vt);
// P (fp16) aliases the retiring K stage (4 warps x 1152 halves = 1 stage).
// ---------------------------------------------------------------------------
#define KHALF 4608             // 64*72 halves per stage
#define PHALF 1152             // 16*72 halves per warp
#define SMEM_A (4 * KHALF * 2) // 36864 bytes (2 K stages + 2 Vt stages)

__global__ __launch_bounds__(128) void attn_mma(float* __restrict__ out)
{
    extern __shared__ __align__(16) __half smh[];
    const uint32_t smb = s2u(smh);

    const int tid  = threadIdx.x;
    const int lane = tid & 31;
    const int wid  = tid >> 5;
    const int h    = blockIdx.y;
    const int b    = blockIdx.z;
    const int q0   = blockIdx.x * 64;
    const int r    = lane >> 2;
    const int c    = lane & 3;
    const int qa   = q0 + wid * 16 + r;          // absolute query (and +8)

    // Q fragments (fp16): 4 k-steps x 4 regs
    uint32_t aq[4][4];
    {
        const __half* q_lo = g_qh + ((size_t)qa * BATCH + b) * DMODEL + h * HDIM;
        const __half* q_hi = q_lo + (size_t)8 * BATCH * DMODEL;
#pragma unroll
        for (int kt = 0; kt < 4; kt++) {
            aq[kt][0] = *(const uint32_t*)(q_lo + 16 * kt + 2 * c);
            aq[kt][1] = *(const uint32_t*)(q_hi + 16 * kt + 2 * c);
            aq[kt][2] = *(const uint32_t*)(q_lo + 16 * kt + 2 * c + 8);
            aq[kt][3] = *(const uint32_t*)(q_hi + 16 * kt + 2 * c + 8);
        }
    }

    float oacc[8][4];
#pragma unroll
    for (int nt = 0; nt < 8; nt++)
#pragma unroll
        for (int i = 0; i < 4; i++) oacc[nt][i] = 0.f;
    float m0 = -1e30f, m1 = -1e30f, l0 = 0.f, l1 = 0.f;

    const int t_start = (q0 >= WSZ) ? 0 : ((WSZ - q0) >> 6);
    const int nch     = 5 - t_start;
    const int kbase0  = q0 - WSZ + t_start * 64;   // >= 0, 64-aligned

    auto load_chunk = [&](int u) {
        const int cb = kbase0 + u * 64;
        const uint32_t kd = smb + (uint32_t)((u & 1) * KHALF) * 2;
        const uint32_t vd = smb + (uint32_t)((2 + (u & 1)) * KHALF) * 2;
        // K: 64 keys x 8 chunks (16B = 8 halves)
#pragma unroll
        for (int it = 0; it < 4; it++) {
            const int f   = tid + 128 * it;      // 0..511
            const int row = f >> 3;
            const int ch  = f & 7;
            cpa16(kd + (uint32_t)(row * 72 + ch * 8) * 2,
                  g_kh + ((size_t)(cb + row) * BATCH + b) * DMODEL
                       + h * HDIM + ch * 8);
        }
        // Vt: 64 dims x 8 chunks
#pragma unroll
        for (int it = 0; it < 4; it++) {
            const int f = tid + 128 * it;
            const int d  = f >> 3;
            const int ch = f & 7;
            cpa16(vd + (uint32_t)(d * 72 + ch * 8) * 2,
                  g_vt + ((size_t)(h * HDIM + d) * BATCH + b) * S_LEN
                       + cb + ch * 8);
        }
        asm volatile("cp.async.commit_group;" ::: "memory");
    };

    load_chunk(0);
    if (nch > 1) load_chunk(1);
    else asm volatile("cp.async.commit_group;" ::: "memory");

    const float NEGINF = __int_as_float(0xff800000);

    for (int u = 0; u < nch; u++) {
        asm volatile("cp.async.wait_group 1;" ::: "memory");
        __syncthreads();

        const __half* Kb = smh + (u & 1) * KHALF;
        const __half* Vb = smh + (2 + (u & 1)) * KHALF;
        __half* Pw = smh + (u & 1) * KHALF + wid * PHALF;   // alias into Kb
        const int cb = kbase0 + u * 64;

        // ---- S = Q K^T ----
        float sacc[8][4];
#pragma unroll
        for (int nt = 0; nt < 8; nt++)
#pragma unroll
            for (int i = 0; i < 4; i++) sacc[nt][i] = 0.f;
#pragma unroll
        for (int kt = 0; kt < 4; kt++) {
#pragma unroll
            for (int nt = 0; nt < 8; nt++) {
                uint32_t bf[2];
                const __half* kp = Kb + (8 * nt + r) * 72 + 16 * kt + 2 * c;
                bf[0] = *(const uint32_t*)(kp);
                bf[1] = *(const uint32_t*)(kp + 8);
                mma_f16(sacc[nt], aq[kt], bf);
            }
        }

        // ---- mask + rowmax ----
        float rmax0 = NEGINF, rmax1 = NEGINF;
#pragma unroll
        for (int nt = 0; nt < 8; nt++) {
            const int j = cb + 8 * nt + 2 * c;
            sacc[nt][0] = ((unsigned)(qa - j)         <= WSZ) ? sacc[nt][0] : NEGINF;
            sacc[nt][1] = ((unsigned)(qa - j - 1)     <= WSZ) ? sacc[nt][1] : NEGINF;
            sacc[nt][2] = ((unsigned)(qa + 8 - j)     <= WSZ) ? sacc[nt][2] : NEGINF;
            sacc[nt][3] = ((unsigned)(qa + 8 - j - 1) <= WSZ) ? sacc[nt][3] : NEGINF;
            rmax0 = fmaxf(rmax0, fmaxf(sacc[nt][0], sacc[nt][1]));
            rmax1 = fmaxf(rmax1, fmaxf(sacc[nt][2], sacc[nt][3]));
        }
        rmax0 = fmaxf(rmax0, __shfl_xor_sync(0xffffffffu, rmax0, 1));
        rmax0 = fmaxf(rmax0, __shfl_xor_sync(0xffffffffu, rmax0, 2));
        rmax1 = fmaxf(rmax1, __shfl_xor_sync(0xffffffffu, rmax1, 1));
        rmax1 = fmaxf(rmax1, __shfl_xor_sync(0xffffffffu, rmax1, 2));

        const float mn0 = fmaxf(m0, rmax0), mn1 = fmaxf(m1, rmax1);
        const float f0 = __expf(m0 - mn0), f1 = __expf(m1 - mn1);
        m0 = mn0; m1 = mn1;

        // all warps must finish reading Kb before P overwrites it
        __syncthreads();

        // ---- exp, rowsum, P(fp16) -> retired K space ----
        float rs0 = 0.f, rs1 = 0.f;
#pragma unroll
        for (int nt = 0; nt < 8; nt++) {
            const float p00 = __expf(sacc[nt][0] - m0);
            const float p01 = __expf(sacc[nt][1] - m0);
            const float p10 = __expf(sacc[nt][2] - m1);
            const float p11 = __expf(sacc[nt][3] - m1);
            rs0 += p00 + p01;
            rs1 += p10 + p11;
            *(__half2*)&Pw[r * 72 + 8 * nt + 2 * c] =
                __floats2half2_rn(p00, p01);
            *(__half2*)&Pw[(r + 8) * 72 + 8 * nt + 2 * c] =
                __floats2half2_rn(p10, p11);
        }
        rs0 += __shfl_xor_sync(0xffffffffu, rs0, 1);
        rs0 += __shfl_xor_sync(0xffffffffu, rs0, 2);
        rs1 += __shfl_xor_sync(0xffffffffu, rs1, 1);
        rs1 += __shfl_xor_sync(0xffffffffu, rs1, 2);
        l0 = l0 * f0 + rs0;
        l1 = l1 * f1 + rs1;
#pragma unroll
        for (int nt = 0; nt < 8; nt++) {
            oacc[nt][0] *= f0; oacc[nt][1] *= f0;
            oacc[nt][2] *= f1; oacc[nt][3] *= f1;
        }
        __syncwarp();   // P store -> P load visibility within warp

        // ---- O += P V  (A = P[16x64], B = Vt[dim][key]) ----
#pragma unroll
        for (int kt = 0; kt < 4; kt++) {
            uint32_t ap[4];
            ap[0] = *(const uint32_t*)&Pw[r * 72 + 16 * kt + 2 * c];
            ap[1] = *(const uint32_t*)&Pw[(r + 8) * 72 + 16 * kt + 2 * c];
            ap[2] = *(const uint32_t*)&Pw[r * 72 + 16 * kt + 2 * c + 8];
            ap[3] = *(const uint32_t*)&Pw[(r + 8) * 72 + 16 * kt + 2 * c + 8];
#pragma unroll
            for (int nt = 0; nt < 8; nt++) {
                uint32_t bf[2];
                const __half* vp = Vb + (8 * nt + r) * 72 + 16 * kt + 2 * c;
                bf[0] = *(const uint32_t*)(vp);
                bf[1] = *(const uint32_t*)(vp + 8);
                mma_f16(oacc[nt], ap, bf);
            }
        }

        __syncthreads();
        if (u + 2 < nch) load_chunk(u + 2);
        else asm volatile("cp.async.commit_group;" ::: "memory");
    }

    // ---- epilogue ----
    const float i0 = 1.f / l0, i1 = 1.f / l1;
    float* o_lo = out + ((size_t)qa * BATCH + b) * DMODEL + h * HDIM;
    float* o_hi = o_lo + (size_t)8 * BATCH * DMODEL;
#pragma unroll
    for (int nt = 0; nt < 8; nt++) {
        *(float2*)&o_lo[8 * nt + 2 * c] =
            make_float2(oacc[nt][0] * i0, oacc[nt][1] * i0);
        *(float2*)&o_hi[8 * nt + 2 * c] =
            make_float2(oacc[nt][2] * i1, oacc[nt][3] * i1);
    }
}

// ---------------------------------------------------------------------------
extern "C" void kernel_launch(void* const* d_in, const int* in_sizes, int n_in,
                              void* d_out, int out_size)
{
    const float* val = (const float*)d_in[0];
    const float* Wq  = (const float*)d_in[1];
    const float* bq  = (const float*)d_in[2];
    const float* Wk  = (const float*)d_in[3];
    const float* bk  = (const float*)d_in[4];
    const float* Wv  = (const float*)d_in[5];
    const float* bv  = (const float*)d_in[6];
    float* out = (float*)d_out;

    cudaFuncSetAttribute(qkv_gemm,
                         cudaFuncAttributeMaxDynamicSharedMemorySize, SMEM_G);
    cudaFuncSetAttribute(attn_mma,
                         cudaFuncAttributeMaxDynamicSharedMemorySize, SMEM_A);

    conv_val<<<(size_t)NROWS * DMODEL / 1024, 256>>>(val);
    conv_w<<<dim3(DMODEL / 32, DMODEL / 32, 3), 256>>>(Wq, Wk, Wv);

    dim3 g1(DMODEL / GN, NROWS / GM, 3);    // 6 x 32 x 3
    qkv_gemm<<<g1, 256, SMEM_G>>>(bq, bk, bv);

    transpose_v<<<dim3(NROWS / 64, DMODEL / 64), 256>>>();

    dim3 g2(S_LEN / 64, NHEAD, BATCH);      // 64 x 12 x 2
    attn_mma<<<g2, 128, SMEM_A>>>(out);
}